// round 2
// baseline (speedup 1.0000x reference)
#include <cuda_runtime.h>
#include <math.h>

// ---------------- problem constants ----------------
#define NHD   32          // heads
#define HD    128         // head dim
#define BSB   4           // batch
#define QL    16          // q len
#define CL    4096        // cache len
#define TTOT  (CL + QL)   // 4112
#define DIMD  4096
#define MROWS (BSB * QL)  // 64

#define VOFF  ((long)BSB * TTOT * NHD * HD)   // 67,371,008
#define OOFF  (2l * VOFF)                     // 134,742,016

#define INV_SQRT_HD 0.08838834764831845f

// ---------------- scratch (device globals, no allocs) ----------------
__device__ float g_qkv[3l * MROWS * DIMD];   // raw xq|xk|xv projections
__device__ float g_xq [MROWS * DIMD];        // roped Q
__device__ float g_attn[MROWS * DIMD];       // attention output (pre out-proj)

// ---------------- packed f32x2 helpers (sm_103a FFMA2) ----------------
__device__ __forceinline__ unsigned long long ffma2(unsigned long long a,
                                                    unsigned long long b,
                                                    unsigned long long c) {
    unsigned long long d;
    asm("fma.rn.f32x2 %0, %1, %2, %3;" : "=l"(d) : "l"(a), "l"(b), "l"(c));
    return d;
}
__device__ __forceinline__ unsigned long long mul2(unsigned long long a,
                                                   unsigned long long b) {
    unsigned long long d;
    asm("mul.rn.f32x2 %0, %1, %2;" : "=l"(d) : "l"(a), "l"(b));
    return d;
}
__device__ __forceinline__ unsigned long long pack2(float x, float y) {
    unsigned long long u;
    asm("mov.b64 %0, {%1, %2};" : "=l"(u) : "f"(x), "f"(y));
    return u;
}
__device__ __forceinline__ void unpack2(unsigned long long u, float& x, float& y) {
    asm("mov.b64 {%0, %1}, %2;" : "=f"(x), "=f"(y) : "l"(u));
}

// ---------------- skinny GEMM: C[64, n-tile] = A[64,4096] @ W[n,:]^T ----------------
// block: 128 threads, BN=32 output columns, BK=32, full M=64.
// per-thread tile TM=4 x TN=4, k accumulated as packed f32x2 pairs.
__device__ __forceinline__ void gemm64_body(const float* __restrict__ A,
                                            const float* __restrict__ W,
                                            float* __restrict__ C,
                                            int n0) {
    __shared__ float As[64][36];
    __shared__ float Ws[32][36];
    const int tid = threadIdx.x;
    const int mg = tid >> 3;   // 0..15 -> m = mg + 16*i
    const int ng = tid & 7;    // 0..7  -> n = ng + 8*j

    unsigned long long acc[4][4];
#pragma unroll
    for (int i = 0; i < 4; i++)
#pragma unroll
        for (int j = 0; j < 4; j++) acc[i][j] = 0ull;

    for (int k0 = 0; k0 < DIMD; k0 += 32) {
        // load A tile: 64x32 = 512 float4 / 128 thr = 4 each
#pragma unroll
        for (int i = 0; i < 4; i++) {
            int idx = tid + i * 128;
            int m = idx >> 3, k4 = idx & 7;
            float4 v = *reinterpret_cast<const float4*>(&A[m * DIMD + k0 + k4 * 4]);
            *reinterpret_cast<float4*>(&As[m][k4 * 4]) = v;
        }
        // load W tile: 32x32 = 256 float4 / 128 thr = 2 each
#pragma unroll
        for (int i = 0; i < 2; i++) {
            int idx = tid + i * 128;
            int n = idx >> 3, k4 = idx & 7;
            float4 v = *reinterpret_cast<const float4*>(&W[(long)(n0 + n) * DIMD + k0 + k4 * 4]);
            *reinterpret_cast<float4*>(&Ws[n][k4 * 4]) = v;
        }
        __syncthreads();
#pragma unroll
        for (int kk = 0; kk < 32; kk += 2) {
            unsigned long long a[4], bb[4];
#pragma unroll
            for (int i = 0; i < 4; i++)
                a[i] = *reinterpret_cast<const unsigned long long*>(&As[mg + 16 * i][kk]);
#pragma unroll
            for (int j = 0; j < 4; j++)
                bb[j] = *reinterpret_cast<const unsigned long long*>(&Ws[ng + 8 * j][kk]);
#pragma unroll
            for (int i = 0; i < 4; i++)
#pragma unroll
                for (int j = 0; j < 4; j++)
                    acc[i][j] = ffma2(a[i], bb[j], acc[i][j]);
        }
        __syncthreads();
    }
#pragma unroll
    for (int i = 0; i < 4; i++)
#pragma unroll
        for (int j = 0; j < 4; j++) {
            float lo, hi;
            unpack2(acc[i][j], lo, hi);
            C[(long)(mg + 16 * i) * DIMD + n0 + ng + 8 * j] = lo + hi;
        }
}

__global__ void gemm_qkv_kernel(const float* __restrict__ x,
                                const float* __restrict__ wq,
                                const float* __restrict__ wk,
                                const float* __restrict__ wv) {
    const float* W = (blockIdx.y == 0) ? wq : ((blockIdx.y == 1) ? wk : wv);
    float* C = g_qkv + (long)blockIdx.y * MROWS * DIMD;
    gemm64_body(x, W, C, blockIdx.x * 32);
}

__global__ void gemm_out_kernel(const float* __restrict__ wo, float* __restrict__ C) {
    gemm64_body(g_attn, wo, C, blockIdx.x * 32);
}

// ---------------- RoPE + scatter new K/V rows into d_out ----------------
// one thread = one (row, head, pair-index) across all 3 matrices
__global__ void rope_scatter_kernel(const float* __restrict__ fc,
                                    const float* __restrict__ fs,
                                    float* __restrict__ dout) {
    int idx = blockIdx.x * 256 + threadIdx.x;  // < 64 * 32 * 64 = 131072
    int row = idx >> 11;        // 0..63  (b*16 + q)
    int p   = idx & 2047;
    int h   = p >> 6;
    int i   = p & 63;
    int b = row >> 4, q = row & 15;
    int col = h * HD + 2 * i;
    const long SZ = (long)MROWS * DIMD;
    float c = fc[q * 64 + i], s = fs[q * 64 + i];

    long src = (long)row * DIMD + col;
    // Q (roped) -> g_xq
    float q0 = g_qkv[src], q1 = g_qkv[src + 1];
    g_xq[src]     = q0 * c - q1 * s;
    g_xq[src + 1] = q0 * s + q1 * c;
    // K (roped) -> d_out k_new row (CL + q)
    float k0 = g_qkv[SZ + src], k1 = g_qkv[SZ + src + 1];
    long dst = (((long)(b * TTOT + CL + q)) * NHD + h) * HD + 2 * i;
    dout[dst]        = k0 * c - k1 * s;
    dout[dst + 1]    = k0 * s + k1 * c;
    // V (plain) -> d_out v_new
    dout[VOFF + dst]     = g_qkv[2 * SZ + src];
    dout[VOFF + dst + 1] = g_qkv[2 * SZ + src + 1];
}

// ---------------- flash attention + fused cache copy ----------------
// grid 128 = (b,h). 128 threads. Tt=32 tile over T=4112.
__global__ void attn_kernel(const float* __restrict__ k_cache,
                            const float* __restrict__ v_cache,
                            const float* __restrict__ mask,
                            float* __restrict__ dout) {
    const int bh = blockIdx.x;
    const int b = bh >> 5, h = bh & 31;

    __shared__ float Qs[16][132];
    __shared__ float Ks[32][132];
    __shared__ float Vs[32][132];
    __shared__ float Ss[16][33];
    __shared__ float m_s[16], l_s[16], corr_s[16];

    const int tid = threadIdx.x;
    const int tq = tid >> 3, td = tid & 7;     // PV mapping: q=tq, d0=td*16
    const int d0 = td * 16;
    const int qg = tid >> 4, tg = tid & 15;    // S mapping: q=2qg+i, t=tg+16j

    // load Q tile (roped)
#pragma unroll
    for (int i = 0; i < 4; i++) {
        int idx = tid + i * 128;               // 512 float4
        int q = idx >> 5, c4 = idx & 31;
        float4 v = *reinterpret_cast<const float4*>(&g_xq[(long)(b * 16 + q) * DIMD + h * HD + c4 * 4]);
        *reinterpret_cast<float4*>(&Qs[q][c4 * 4]) = v;
    }
    if (tid < 16) { m_s[tid] = -1e30f; l_s[tid] = 0.0f; }

    unsigned long long O2[8];
#pragma unroll
    for (int jj = 0; jj < 8; jj++) O2[jj] = 0ull;

    float* knew = dout;
    float* vnew = dout + VOFF;
    __syncthreads();

    for (int t0 = 0; t0 < TTOT; t0 += 32) {
        const int rows = min(32, TTOT - t0);
        // ---- load K/V tile into smem; fused copy cache -> k_new/v_new ----
#pragma unroll
        for (int i = 0; i < 8; i++) {
            int idx = tid + i * 128;           // 1024 float4 per matrix
            int r = idx >> 5, c4 = idx & 31;
            int t = t0 + r;
            if (r < rows) {
                long dst = (((long)(b * TTOT + t)) * NHD + h) * HD + c4 * 4;
                if (t < CL) {
                    long src = (((long)(b * CL + t)) * NHD + h) * HD + c4 * 4;
                    float4 kv = *reinterpret_cast<const float4*>(&k_cache[src]);
                    *reinterpret_cast<float4*>(&Ks[r][c4 * 4]) = kv;
                    *reinterpret_cast<float4*>(&knew[dst]) = kv;
                    float4 vv = *reinterpret_cast<const float4*>(&v_cache[src]);
                    *reinterpret_cast<float4*>(&Vs[r][c4 * 4]) = vv;
                    *reinterpret_cast<float4*>(&vnew[dst]) = vv;
                } else {  // new rows already in d_out (rope kernel)
                    *reinterpret_cast<float4*>(&Ks[r][c4 * 4]) = *reinterpret_cast<const float4*>(&knew[dst]);
                    *reinterpret_cast<float4*>(&Vs[r][c4 * 4]) = *reinterpret_cast<const float4*>(&vnew[dst]);
                }
            }
        }
        __syncthreads();

        // ---- S = Q @ K^T (per thread: 2 q x 2 t, packed k-pairs) ----
        unsigned long long sacc[2][2] = {{0ull, 0ull}, {0ull, 0ull}};
#pragma unroll 16
        for (int kk = 0; kk < HD; kk += 2) {
            unsigned long long a0 = *reinterpret_cast<const unsigned long long*>(&Qs[2 * qg][kk]);
            unsigned long long a1 = *reinterpret_cast<const unsigned long long*>(&Qs[2 * qg + 1][kk]);
            unsigned long long b0 = *reinterpret_cast<const unsigned long long*>(&Ks[tg][kk]);
            unsigned long long b1 = *reinterpret_cast<const unsigned long long*>(&Ks[tg + 16][kk]);
            sacc[0][0] = ffma2(a0, b0, sacc[0][0]);
            sacc[0][1] = ffma2(a0, b1, sacc[0][1]);
            sacc[1][0] = ffma2(a1, b0, sacc[1][0]);
            sacc[1][1] = ffma2(a1, b1, sacc[1][1]);
        }
#pragma unroll
        for (int i = 0; i < 2; i++)
#pragma unroll
            for (int j = 0; j < 2; j++) {
                float lo, hi;
                unpack2(sacc[i][j], lo, hi);
                Ss[2 * qg + i][tg + 16 * j] = (lo + hi) * INV_SQRT_HD;
            }
        __syncthreads();

        // ---- online softmax (16 row threads) ----
        if (tid < 16) {
            const int q = tid;
            float mx = m_s[q];
            float sv[32];
            float tm = mx;
#pragma unroll
            for (int t = 0; t < 32; t++) {
                bool valid = (t < rows);
                sv[t] = valid ? (Ss[q][t] + mask[q * TTOT + t0 + t]) : -1e30f;
                tm = fmaxf(tm, sv[t]);
            }
            float corr = __expf(mx - tm);
            float l = l_s[q] * corr;
#pragma unroll
            for (int t = 0; t < 32; t++) {
                float pe = __expf(sv[t] - tm);
                Ss[q][t] = pe;
                l += pe;
            }
            m_s[q] = tm; l_s[q] = l; corr_s[q] = corr;
        }
        __syncthreads();

        // ---- O = corr*O + P @ V (per thread: q=tq, 16 d values) ----
        {
            float corr = corr_s[tq];
            unsigned long long corr2 = pack2(corr, corr);
#pragma unroll
            for (int jj = 0; jj < 8; jj++) O2[jj] = mul2(O2[jj], corr2);
#pragma unroll 8
            for (int t = 0; t < 32; t++) {
                if (t >= rows) break;
                float pv = Ss[tq][t];
                unsigned long long pp = pack2(pv, pv);
#pragma unroll
                for (int jj = 0; jj < 8; jj++)
                    O2[jj] = ffma2(pp, *reinterpret_cast<const unsigned long long*>(&Vs[t][d0 + 2 * jj]), O2[jj]);
            }
        }
        __syncthreads();
    }

    // epilogue: normalize, write to g_attn at [b*16+q, h*128 + d]
    const float linv = 1.0f / l_s[tq];
    long obase = (long)(b * 16 + tq) * DIMD + h * HD + d0;
#pragma unroll
    for (int jj = 0; jj < 8; jj++) {
        float lo, hi;
        unpack2(O2[jj], lo, hi);
        g_attn[obase + 2 * jj]     = lo * linv;
        g_attn[obase + 2 * jj + 1] = hi * linv;
    }
}

// ---------------- launch ----------------
extern "C" void kernel_launch(void* const* d_in, const int* in_sizes, int n_in,
                              void* d_out, int out_size) {
    const float* x    = (const float*)d_in[0];
    const float* kc   = (const float*)d_in[1];
    const float* vc   = (const float*)d_in[2];
    const float* fc   = (const float*)d_in[3];
    const float* fs   = (const float*)d_in[4];
    const float* mask = (const float*)d_in[5];
    const float* wq   = (const float*)d_in[6];
    const float* wk   = (const float*)d_in[7];
    const float* wv   = (const float*)d_in[8];
    const float* wo   = (const float*)d_in[9];
    float* out = (float*)d_out;

    // 1) QKV projections -> g_qkv
    gemm_qkv_kernel<<<dim3(DIMD / 32, 3), 128>>>(x, wq, wk, wv);
    // 2) RoPE Q->g_xq, roped K + V new rows -> d_out tails
    rope_scatter_kernel<<<(MROWS * NHD * 64) / 256, 256>>>(fc, fs, out);
    // 3) flash attention + fused cache copy -> g_attn, d_out k_new/v_new
    attn_kernel<<<BSB * NHD, 128>>>(kc, vc, mask, out);
    // 4) output projection -> d_out out region
    gemm_out_kernel<<<DIMD / 32, 128>>>(wo, out + OOFF);
}

// round 3
// speedup vs baseline: 2.8507x; 2.8507x over previous
#include <cuda_runtime.h>
#include <math.h>

typedef unsigned long long u64;

// ---------------- problem constants ----------------
#define NHD   32
#define HD    128
#define BSB   4
#define QL    16
#define CL    4096
#define TTOT  (CL + QL)        // 4112
#define DIMD  4096
#define MROWS 64
#define NS    16               // attention kv splits (16*257 = 4112)
#define RANGE 257
#define TT    32               // attention time tile
#define KSPLIT 4
#define KLEN  (DIMD / KSPLIT)  // 1024

#define VOFF  ((long)BSB * TTOT * NHD * HD)
#define OOFF  (2l * VOFF)
#define INV_SQRT_HD 0.08838834764831845f

// ---------------- scratch ----------------
__device__ float g_qkvp[KSPLIT][MROWS * 3 * DIMD];  // qkv partial sums (cols 0..12287)
__device__ float g_xq  [MROWS * DIMD];              // roped Q
__device__ float g_attn[MROWS * DIMD];              // attention out (pre-proj)
__device__ float g_op  [KSPLIT][MROWS * DIMD];      // out-proj partials
__device__ float g_ao  [(long)BSB * NHD * NS * QL * HD]; // attn partial O
__device__ float g_am  [BSB * NHD * NS * QL];
__device__ float g_al  [BSB * NHD * NS * QL];

// ---------------- f32x2 helpers ----------------
__device__ __forceinline__ u64 ffma2(u64 a, u64 b, u64 c) {
    u64 d; asm("fma.rn.f32x2 %0, %1, %2, %3;" : "=l"(d) : "l"(a), "l"(b), "l"(c));
    return d;
}
__device__ __forceinline__ u64 mul2(u64 a, u64 b) {
    u64 d; asm("mul.rn.f32x2 %0, %1, %2;" : "=l"(d) : "l"(a), "l"(b));
    return d;
}
__device__ __forceinline__ u64 pack2(float x, float y) {
    u64 u; asm("mov.b64 %0, {%1, %2};" : "=l"(u) : "f"(x), "f"(y));
    return u;
}
__device__ __forceinline__ void unpack2(u64 u, float& x, float& y) {
    asm("mov.b64 {%0, %1}, %2;" : "=f"(x), "=f"(y) : "l"(u));
}

// ---------------- split-K skinny GEMM body ----------------
// C[64 rows, 32 cols at ccol0] += A[64, k0:k0+KLEN] @ W[nw0:nw0+32, k0:k0+KLEN]^T
__device__ __forceinline__ void gemm64_body(const float* __restrict__ A,
                                            const float* __restrict__ W,
                                            float* __restrict__ C,
                                            int nw0, long ccol0, int cstride, int k0) {
    __shared__ float As[64][36];
    __shared__ float Ws[32][36];
    const int tid = threadIdx.x;
    const int mg = tid >> 3;   // m = mg + 16*i
    const int ng = tid & 7;    // n = ng + 8*j

    u64 acc[4][4];
#pragma unroll
    for (int i = 0; i < 4; i++)
#pragma unroll
        for (int j = 0; j < 4; j++) acc[i][j] = 0ull;

    for (int kb = k0; kb < k0 + KLEN; kb += 32) {
#pragma unroll
        for (int i = 0; i < 4; i++) {
            int idx = tid + i * 128;
            int m = idx >> 3, k4 = idx & 7;
            float4 v = *reinterpret_cast<const float4*>(&A[(long)m * DIMD + kb + k4 * 4]);
            *reinterpret_cast<float4*>(&As[m][k4 * 4]) = v;
        }
#pragma unroll
        for (int i = 0; i < 2; i++) {
            int idx = tid + i * 128;
            int n = idx >> 3, k4 = idx & 7;
            float4 v = *reinterpret_cast<const float4*>(&W[(long)(nw0 + n) * DIMD + kb + k4 * 4]);
            *reinterpret_cast<float4*>(&Ws[n][k4 * 4]) = v;
        }
        __syncthreads();
#pragma unroll
        for (int kk = 0; kk < 32; kk += 2) {
            u64 a[4], bb[4];
#pragma unroll
            for (int i = 0; i < 4; i++)
                a[i] = *reinterpret_cast<const u64*>(&As[mg + 16 * i][kk]);
#pragma unroll
            for (int j = 0; j < 4; j++)
                bb[j] = *reinterpret_cast<const u64*>(&Ws[ng + 8 * j][kk]);
#pragma unroll
            for (int i = 0; i < 4; i++)
#pragma unroll
                for (int j = 0; j < 4; j++)
                    acc[i][j] = ffma2(a[i], bb[j], acc[i][j]);
        }
        __syncthreads();
    }
#pragma unroll
    for (int i = 0; i < 4; i++)
#pragma unroll
        for (int j = 0; j < 4; j++) {
            float lo, hi;
            unpack2(acc[i][j], lo, hi);
            C[(long)(mg + 16 * i) * cstride + ccol0 + ng + 8 * j] = lo + hi;
        }
}

__global__ void gemm_qkv_kernel(const float* __restrict__ x,
                                const float* __restrict__ wq,
                                const float* __restrict__ wk,
                                const float* __restrict__ wv) {
    int ng = blockIdx.x * 32;          // 0..12287
    int mtx = ng >> 12;
    int nw = ng & 4095;
    const float* W = (mtx == 0) ? wq : ((mtx == 1) ? wk : wv);
    gemm64_body(x, W, g_qkvp[blockIdx.y], nw, ng, 3 * DIMD, blockIdx.y * KLEN);
}

__global__ void gemm_out_kernel(const float* __restrict__ wo) {
    int n0 = blockIdx.x * 32;
    gemm64_body(g_attn, wo, g_op[blockIdx.y], n0, n0, DIMD, blockIdx.y * KLEN);
}

__global__ void reduce_out_kernel(float* __restrict__ out) {
    int idx = blockIdx.x * 256 + threadIdx.x;  // < 262144
    out[idx] = g_op[0][idx] + g_op[1][idx] + g_op[2][idx] + g_op[3][idx];
}

// ---------------- RoPE + split-K reduce + scatter ----------------
__global__ void rope_scatter_kernel(const float* __restrict__ fc,
                                    const float* __restrict__ fs,
                                    float* __restrict__ dout) {
    int idx = blockIdx.x * 256 + threadIdx.x;  // < 131072
    int row = idx >> 11;        // b*16+q
    int p   = idx & 2047;
    int h   = p >> 6;
    int i   = p & 63;
    int b = row >> 4, q = row & 15;
    int col = h * HD + 2 * i;
    float c = fc[q * 64 + i], s = fs[q * 64 + i];

    float q0 = 0.f, q1 = 0.f, k0 = 0.f, k1 = 0.f, v0 = 0.f, v1 = 0.f;
#pragma unroll
    for (int sp = 0; sp < KSPLIT; sp++) {
        const float* P = g_qkvp[sp] + (long)row * (3 * DIMD);
        q0 += P[col];            q1 += P[col + 1];
        k0 += P[DIMD + col];     k1 += P[DIMD + col + 1];
        v0 += P[2 * DIMD + col]; v1 += P[2 * DIMD + col + 1];
    }
    long dstq = (long)row * DIMD + col;
    g_xq[dstq]     = q0 * c - q1 * s;
    g_xq[dstq + 1] = q0 * s + q1 * c;
    long dst = (((long)(b * TTOT + CL + q)) * NHD + h) * HD + 2 * i;
    dout[dst]            = k0 * c - k1 * s;
    dout[dst + 1]        = k0 * s + k1 * c;
    dout[VOFF + dst]     = v0;
    dout[VOFF + dst + 1] = v1;
}

// ---------------- split-KV flash attention + fused cache copy ----------------
// grid = 128*NS = 2048 CTAs, 256 threads
__global__ void attn_kernel(const float* __restrict__ kc,
                            const float* __restrict__ vc,
                            const float* __restrict__ mask,
                            float* __restrict__ dout) {
    const int blk = blockIdx.x;
    const int bh = blk >> 4, s = blk & 15;
    const int b = bh >> 5, h = bh & 31;
    const int tstart = s * RANGE;
    const int tend   = tstart + RANGE;   // NS*RANGE == TTOT exactly

    __shared__ float Qs[16][130];
    __shared__ float Ks[TT][130];
    __shared__ float Vs[TT][130];
    __shared__ float Ps[16][33];
    __shared__ float m_sh[16], l_sh[16], corr_sh[16];

    const int tid = threadIdx.x;
    const int rq = tid >> 4;       // row 0..15 (S / softmax / O)
    const int rc = tid & 15;       // lane-in-row 0..15

    // load roped Q tile: 16 x 32 float4 = 512 / 256 thr
#pragma unroll
    for (int i = 0; i < 2; i++) {
        int idx = tid + i * 256;
        int q = idx >> 5, c4 = idx & 31;
        float4 v = *reinterpret_cast<const float4*>(&g_xq[(long)(b * 16 + q) * DIMD + h * HD + c4 * 4]);
        *reinterpret_cast<float2*>(&Qs[q][c4 * 4])     = make_float2(v.x, v.y);
        *reinterpret_cast<float2*>(&Qs[q][c4 * 4 + 2]) = make_float2(v.z, v.w);
    }
    if (tid < 16) { m_sh[tid] = -1e30f; l_sh[tid] = 0.0f; }

    u64 O2[4] = {0ull, 0ull, 0ull, 0ull};     // d-pairs at 2*rc + 32*j
    float* knew = dout;
    float* vnew = dout + VOFF;
    __syncthreads();

    for (int t0 = tstart; t0 < tend; t0 += TT) {
        const int rows = min(TT, tend - t0);
        // ---- load K/V tile + fused cache copy ----
#pragma unroll
        for (int i = 0; i < 4; i++) {
            int idx = tid + i * 256;       // 1024 float4 per matrix
            int r = idx >> 5, c4 = idx & 31;
            int t = t0 + r;
            if (r < rows) {
                long dst = (((long)(b * TTOT + t)) * NHD + h) * HD + c4 * 4;
                float4 kv, vv;
                if (t < CL) {
                    long src = (((long)(b * CL + t)) * NHD + h) * HD + c4 * 4;
                    kv = *reinterpret_cast<const float4*>(&kc[src]);
                    vv = *reinterpret_cast<const float4*>(&vc[src]);
                    *reinterpret_cast<float4*>(&knew[dst]) = kv;
                    *reinterpret_cast<float4*>(&vnew[dst]) = vv;
                } else {  // new rows, written by rope kernel
                    kv = *reinterpret_cast<const float4*>(&knew[dst]);
                    vv = *reinterpret_cast<const float4*>(&vnew[dst]);
                }
                *reinterpret_cast<float2*>(&Ks[r][c4 * 4])     = make_float2(kv.x, kv.y);
                *reinterpret_cast<float2*>(&Ks[r][c4 * 4 + 2]) = make_float2(kv.z, kv.w);
                *reinterpret_cast<float2*>(&Vs[r][c4 * 4])     = make_float2(vv.x, vv.y);
                *reinterpret_cast<float2*>(&Vs[r][c4 * 4 + 2]) = make_float2(vv.z, vv.w);
            }
        }
        __syncthreads();

        // ---- S = Q@K^T : thread (rq, rc) -> t in {rc, rc+16} ----
        {
            u64 s0 = 0ull, s1 = 0ull;
#pragma unroll
            for (int kk = 0; kk < HD; kk += 2) {
                u64 a = *reinterpret_cast<const u64*>(&Qs[rq][kk]);
                s0 = ffma2(a, *reinterpret_cast<const u64*>(&Ks[rc][kk]), s0);
                s1 = ffma2(a, *reinterpret_cast<const u64*>(&Ks[rc + 16][kk]), s1);
            }
            float lo, hi;
            unpack2(s0, lo, hi); Ps[rq][rc]      = (lo + hi) * INV_SQRT_HD;
            unpack2(s1, lo, hi); Ps[rq][rc + 16] = (lo + hi) * INV_SQRT_HD;
        }
        __syncthreads();

        // ---- online softmax: 16 threads per row, 2 cols each ----
        {
            float mprev = m_sh[rq];
            float v0 = (rc < rows)      ? Ps[rq][rc]      + mask[rq * TTOT + t0 + rc]      : -1e30f;
            float v1 = (rc + 16 < rows) ? Ps[rq][rc + 16] + mask[rq * TTOT + t0 + rc + 16] : -1e30f;
            float mx = fmaxf(v0, v1);
#pragma unroll
            for (int m = 8; m; m >>= 1) mx = fmaxf(mx, __shfl_xor_sync(0xffffffffu, mx, m));
            float tm = fmaxf(mprev, mx);
            float p0 = __expf(v0 - tm), p1 = __expf(v1 - tm);
            Ps[rq][rc]      = p0;
            Ps[rq][rc + 16] = p1;
            float sum = p0 + p1;
#pragma unroll
            for (int m = 8; m; m >>= 1) sum += __shfl_xor_sync(0xffffffffu, sum, m);
            if (rc == 0) {
                float corr = __expf(mprev - tm);
                m_sh[rq] = tm;
                l_sh[rq] = l_sh[rq] * corr + sum;
                corr_sh[rq] = corr;
            }
        }
        __syncthreads();

        // ---- O = corr*O + P@V : thread (rq, rc), d pairs 2rc + 32j ----
        {
            float corr = corr_sh[rq];
            u64 corr2 = pack2(corr, corr);
#pragma unroll
            for (int j = 0; j < 4; j++) O2[j] = mul2(O2[j], corr2);
#pragma unroll 8
            for (int t = 0; t < rows; t++) {
                float pv = Ps[rq][t];
                u64 pp = pack2(pv, pv);
#pragma unroll
                for (int j = 0; j < 4; j++)
                    O2[j] = ffma2(pp, *reinterpret_cast<const u64*>(&Vs[t][2 * rc + 32 * j]), O2[j]);
            }
        }
        __syncthreads();
    }

    // write partial O (unnormalized) + m,l
    long base = ((long)(bh * NS + s) * 16 + rq) * HD;
#pragma unroll
    for (int j = 0; j < 4; j++) {
        float lo, hi;
        unpack2(O2[j], lo, hi);
        *reinterpret_cast<float2*>(&g_ao[base + 2 * rc + 32 * j]) = make_float2(lo, hi);
    }
    if (tid < 16) {
        g_am[(bh * NS + s) * 16 + tid] = m_sh[tid];
        g_al[(bh * NS + s) * 16 + tid] = l_sh[tid];
    }
}

// ---------------- combine split-KV partials ----------------
__global__ void attn_combine_kernel() {
    const int bh = blockIdx.x;            // 0..127
    const int b = bh >> 5, h = bh & 31;
    const int tid = threadIdx.x;          // 256
    __shared__ float w_sh[16][NS];
    __shared__ float linv_sh[16];

    if (tid < 16) {
        float mm[NS];
        float M = -1e30f;
#pragma unroll
        for (int s = 0; s < NS; s++) {
            mm[s] = g_am[(bh * NS + s) * 16 + tid];
            M = fmaxf(M, mm[s]);
        }
        float L = 0.f;
#pragma unroll
        for (int s = 0; s < NS; s++) {
            float w = __expf(mm[s] - M);
            w_sh[tid][s] = w;
            L += w * g_al[(bh * NS + s) * 16 + tid];
        }
        linv_sh[tid] = 1.0f / L;
    }
    __syncthreads();

    const int q = tid >> 4, d0 = (tid & 15) * 8;
    float acc[8];
#pragma unroll
    for (int j = 0; j < 8; j++) acc[j] = 0.f;
#pragma unroll
    for (int s = 0; s < NS; s++) {
        float w = w_sh[q][s];
        const float* P = &g_ao[((long)(bh * NS + s) * 16 + q) * HD + d0];
#pragma unroll
        for (int j = 0; j < 8; j++) acc[j] += w * P[j];
    }
    float linv = linv_sh[q];
    long ob = (long)(b * 16 + q) * DIMD + h * HD + d0;
#pragma unroll
    for (int j = 0; j < 8; j++) g_attn[ob + j] = acc[j] * linv;
}

// ---------------- launch ----------------
extern "C" void kernel_launch(void* const* d_in, const int* in_sizes, int n_in,
                              void* d_out, int out_size) {
    const float* x    = (const float*)d_in[0];
    const float* kc   = (const float*)d_in[1];
    const float* vc   = (const float*)d_in[2];
    const float* fc   = (const float*)d_in[3];
    const float* fs   = (const float*)d_in[4];
    const float* mask = (const float*)d_in[5];
    const float* wq   = (const float*)d_in[6];
    const float* wk   = (const float*)d_in[7];
    const float* wv   = (const float*)d_in[8];
    const float* wo   = (const float*)d_in[9];
    float* out = (float*)d_out;

    gemm_qkv_kernel<<<dim3(384, KSPLIT), 128>>>(x, wq, wk, wv);
    rope_scatter_kernel<<<512, 256>>>(fc, fs, out);
    attn_kernel<<<BSB * NHD * NS, 256>>>(kc, vc, mask, out);
    attn_combine_kernel<<<BSB * NHD, 256>>>();
    gemm_out_kernel<<<dim3(128, KSPLIT), 128>>>(wo);
    reduce_out_kernel<<<1024, 256>>>(out + OOFF);
}